// round 11
// baseline (speedup 1.0000x reference)
#include <cuda_runtime.h>
#include <cstdint>

// CRF loss: mean_b( logZ_b - gold_b );  B=256, T=1024, C=64
// Scaled-domain forward: p_{t+1} = (E^T p_t) ∘ W_t / c_t,  logZ += log2 c_t.
// TWO independent batch chains per warp (A,B), interleaved in one instruction
// stream so each chain's ~250-cyc serial-exchange latency is hidden by the
// other chain's work. Thread owns tags (lane, lane+32) of both chains; E
// register columns are shared. One __syncwarp per step serves both chains.
// Grid 32 x 128thr = 128 warps = 256 chains. Final reduction fused.

#define BD 256
#define TD 1024
#define CD 64
#define LOG2E 1.4426950408889634f
#define LN2   0.6931471805599453f

__device__ float        g_partial[BD];
__device__ unsigned int g_done = 0;

__device__ __forceinline__ float fast_exp2(float x) {
    float y; asm("ex2.approx.ftz.f32 %0, %1;" : "=f"(y) : "f"(x)); return y;
}
__device__ __forceinline__ float fast_log2(float x) {
    float y; asm("lg2.approx.ftz.f32 %0, %1;" : "=f"(y) : "f"(x)); return y;
}
__device__ __forceinline__ float fast_rcp(float x) {
    float y; asm("rcp.approx.ftz.f32 %0, %1;" : "=f"(y) : "f"(x)); return y;
}
__device__ __forceinline__ unsigned long long pack2(float lo, float hi) {
    unsigned long long r;
    asm("mov.b64 %0, {%1, %2};" : "=l"(r) : "f"(lo), "f"(hi)); return r;
}
__device__ __forceinline__ unsigned long long ffma2(unsigned long long a,
                                                    unsigned long long b,
                                                    unsigned long long c) {
    unsigned long long d;
    asm("fma.rn.f32x2 %0, %1, %2, %3;" : "=l"(d) : "l"(a), "l"(b), "l"(c));
    return d;
}
__device__ __forceinline__ float2 unpack2(unsigned long long v) {
    float2 f;
    asm("mov.b64 {%0, %1}, %2;" : "=f"(f.x), "=f"(f.y) : "l"(v)); return f;
}

// One forward step for BOTH chains. T_/SLOT_ must be compile-time constants.
#define STEP2(T_, SLOT_)                                                       \
    {                                                                          \
        const float WA0 = WrA0[(SLOT_)], WA1 = WrA1[(SLOT_)];                  \
        const float WB0 = WrB0[(SLOT_)], WB1 = WrB1[(SLOT_)];                  \
        const float mtA = mrA[(SLOT_)],  mtB = mrB[(SLOT_)];                   \
        const int tpf = (T_) + 4;                                              \
        if (tpf < TD) {                                                        \
            WrA0[(SLOT_)] = fast_exp2(emA[tpf * CD + j0] * LOG2E);             \
            WrA1[(SLOT_)] = fast_exp2(emA[tpf * CD + j1] * LOG2E);             \
            mrA[(SLOT_)]  = mkA[tpf];                                          \
            WrB0[(SLOT_)] = fast_exp2(emB[tpf * CD + j0] * LOG2E);             \
            WrB1[(SLOT_)] = fast_exp2(emB[tpf * CD + j1] * LOG2E);             \
            mrB[(SLOT_)]  = mkB[tpf];                                          \
        }                                                                      \
        const float* pcA = psh[cAi][cur];                                      \
        const float* pcB = psh[cBi][cur];                                      \
        const float cA = pcA[0], cB = pcB[0];                                  \
        const float rA = fast_rcp(cA), rB = fast_rcp(cB);                      \
        logAccA += fast_log2(cA);                                              \
        logAccB += fast_log2(cB);                                              \
        const float WA0r = WA0 * rA, WA1r = WA1 * rA;                          \
        const float WB0r = WB0 * rB, WB1r = WB1 * rB;                          \
        unsigned long long aA0 = 0ull, aA1 = 0ull, aA2 = 0ull, aA3 = 0ull;     \
        unsigned long long bA0 = 0ull, bA1 = 0ull, bA2 = 0ull, bA3 = 0ull;     \
        unsigned long long aB0 = 0ull, aB1 = 0ull, aB2 = 0ull, aB3 = 0ull;     \
        unsigned long long bB0 = 0ull, bB1 = 0ull, bB2 = 0ull, bB3 = 0ull;     \
        _Pragma("unroll")                                                      \
        for (int i = 0; i < CD; i += 8) {                                      \
            ulonglong2 qaA = *(const ulonglong2*)&pcA[i];                      \
            ulonglong2 qaB = *(const ulonglong2*)&pcB[i];                      \
            ulonglong2 qbA = *(const ulonglong2*)&pcA[i + 4];                  \
            ulonglong2 qbB = *(const ulonglong2*)&pcB[i + 4];                  \
            aA0 = ffma2(qaA.x, E0p[i / 2 + 0], aA0);                           \
            aB0 = ffma2(qaB.x, E0p[i / 2 + 0], aB0);                           \
            bA0 = ffma2(qaA.x, E1p[i / 2 + 0], bA0);                           \
            bB0 = ffma2(qaB.x, E1p[i / 2 + 0], bB0);                           \
            aA1 = ffma2(qaA.y, E0p[i / 2 + 1], aA1);                           \
            aB1 = ffma2(qaB.y, E0p[i / 2 + 1], aB1);                           \
            bA1 = ffma2(qaA.y, E1p[i / 2 + 1], bA1);                           \
            bB1 = ffma2(qaB.y, E1p[i / 2 + 1], bB1);                           \
            aA2 = ffma2(qbA.x, E0p[i / 2 + 2], aA2);                           \
            aB2 = ffma2(qbB.x, E0p[i / 2 + 2], aB2);                           \
            bA2 = ffma2(qbA.x, E1p[i / 2 + 2], bA2);                           \
            bB2 = ffma2(qbB.x, E1p[i / 2 + 2], bB2);                           \
            aA3 = ffma2(qbA.y, E0p[i / 2 + 3], aA3);                           \
            aB3 = ffma2(qbB.y, E0p[i / 2 + 3], aB3);                           \
            bA3 = ffma2(qbA.y, E1p[i / 2 + 3], bA3);                           \
            bB3 = ffma2(qbB.y, E1p[i / 2 + 3], bB3);                           \
        }                                                                      \
        float2 u0, u1, u2, u3;                                                 \
        u0 = unpack2(aA0); u1 = unpack2(aA1);                                  \
        u2 = unpack2(aA2); u3 = unpack2(aA3);                                  \
        const float sA0 = ((u0.x + u0.y) + (u1.x + u1.y))                      \
                        + ((u2.x + u2.y) + (u3.x + u3.y));                     \
        u0 = unpack2(bA0); u1 = unpack2(bA1);                                  \
        u2 = unpack2(bA2); u3 = unpack2(bA3);                                  \
        const float sA1 = ((u0.x + u0.y) + (u1.x + u1.y))                      \
                        + ((u2.x + u2.y) + (u3.x + u3.y));                     \
        u0 = unpack2(aB0); u1 = unpack2(aB1);                                  \
        u2 = unpack2(aB2); u3 = unpack2(aB3);                                  \
        const float sB0 = ((u0.x + u0.y) + (u1.x + u1.y))                      \
                        + ((u2.x + u2.y) + (u3.x + u3.y));                     \
        u0 = unpack2(bB0); u1 = unpack2(bB1);                                  \
        u2 = unpack2(bB2); u3 = unpack2(bB3);                                  \
        const float sB1 = ((u0.x + u0.y) + (u1.x + u1.y))                      \
                        + ((u2.x + u2.y) + (u3.x + u3.y));                     \
        mypA0 = (mtA > 0.f) ? sA0 * WA0r : mypA0 * rA;                         \
        mypA1 = (mtA > 0.f) ? sA1 * WA1r : mypA1 * rA;                         \
        mypB0 = (mtB > 0.f) ? sB0 * WB0r : mypB0 * rB;                         \
        mypB1 = (mtB > 0.f) ? sB1 * WB1r : mypB1 * rB;                         \
        float* pnA = psh[cAi][cur ^ 1];                                        \
        float* pnB = psh[cBi][cur ^ 1];                                        \
        pnA[j0] = mypA0;  pnA[j1] = mypA1;                                     \
        pnB[j0] = mypB0;  pnB[j1] = mypB1;                                     \
        __syncwarp();                                                          \
        cur ^= 1;                                                              \
    }

__global__ __launch_bounds__(128, 1)
void crf_fused_kernel(const float* __restrict__ emissions,
                      const float* __restrict__ transitions,
                      const float* __restrict__ start_t,
                      const float* __restrict__ end_t,
                      const int*   __restrict__ tags,
                      const float* __restrict__ mask,
                      float*       __restrict__ out)
{
    __shared__ __align__(16) float psh[8][2][CD];  // [chain][buf][tag]
    __shared__ float        rsm[4];
    __shared__ unsigned int last_flag;

    const int w    = threadIdx.x >> 5;     // warp 0..3
    const int lane = threadIdx.x & 31;
    const int cAi  = 2 * w, cBi = 2 * w + 1;
    const int bA   = blockIdx.x * 8 + cAi; // batches of this warp
    const int bB   = bA + 1;
    const int j0   = lane;
    const int j1   = lane + 32;

    const float* emA = emissions + (size_t)bA * TD * CD;
    const float* emB = emissions + (size_t)bB * TD * CD;
    const float* mkA = mask      + (size_t)bA * TD;
    const float* mkB = mask      + (size_t)bB * TD;

    // ---- packed E columns (shared by both chains) ----
    unsigned long long E0p[CD / 2], E1p[CD / 2];
    #pragma unroll
    for (int k = 0; k < CD / 2; k++) {
        const float* r0 = transitions + (2 * k)     * CD;
        const float* r1 = transitions + (2 * k + 1) * CD;
        E0p[k] = pack2(fast_exp2(r0[j0] * LOG2E), fast_exp2(r1[j0] * LOG2E));
        E1p[k] = pack2(fast_exp2(r0[j1] * LOG2E), fast_exp2(r1[j1] * LOG2E));
    }

    // ---- gold scores (both chains) ----
    float goldA, goldB;
    {
        const int* tgA = tags + (size_t)bA * TD;
        const int* tgB = tags + (size_t)bB * TD;
        float gpA = 0.f, gpB = 0.f;
        int   cntA = 0,  cntB = 0;
        for (int t = lane; t < TD; t += 32) {
            float mA = mkA[t], mB = mkB[t];
            cntA += (int)mA; cntB += (int)mB;
            if (t >= 1) {
                int ta = tgA[t], pa = tgA[t - 1];
                int tb2 = tgB[t], pb = tgB[t - 1];
                gpA += mA * (emA[t * CD + ta]  + transitions[pa * CD + ta]);
                gpB += mB * (emB[t * CD + tb2] + transitions[pb * CD + tb2]);
            }
        }
        #pragma unroll
        for (int off = 16; off; off >>= 1) {
            gpA  += __shfl_xor_sync(0xffffffffu, gpA,  off);
            gpB  += __shfl_xor_sync(0xffffffffu, gpB,  off);
            cntA += __shfl_xor_sync(0xffffffffu, cntA, off);
            cntB += __shfl_xor_sync(0xffffffffu, cntB, off);
        }
        int liA = cntA - 1; if (liA < 0) liA = 0;
        int liB = cntB - 1; if (liB < 0) liB = 0;
        const int fA = tgA[0], lA = tgA[liA];
        const int fB = tgB[0], lB = tgB[liB];
        goldA = gpA + start_t[fA] + emA[fA] + end_t[lA];
        goldB = gpB + start_t[fB] + emB[fB] + end_t[lB];
    }

    // ---- init (t = 0), linear domain ----
    float mypA0 = fast_exp2((start_t[j0] + emA[j0]) * LOG2E);
    float mypA1 = fast_exp2((start_t[j1] + emA[j1]) * LOG2E);
    float mypB0 = fast_exp2((start_t[j0] + emB[j0]) * LOG2E);
    float mypB1 = fast_exp2((start_t[j1] + emB[j1]) * LOG2E);
    psh[cAi][0][j0] = mypA0;  psh[cAi][0][j1] = mypA1;
    psh[cBi][0][j0] = mypB0;  psh[cBi][0][j1] = mypB1;

    // ---- prefetch rings (4 deep per chain) ----
    float WrA0[4], WrA1[4], mrA[4];
    float WrB0[4], WrB1[4], mrB[4];
    #pragma unroll
    for (int t0 = 1; t0 <= 4; t0++) {
        WrA0[t0 & 3] = fast_exp2(emA[t0 * CD + j0] * LOG2E);
        WrA1[t0 & 3] = fast_exp2(emA[t0 * CD + j1] * LOG2E);
        mrA[t0 & 3]  = mkA[t0];
        WrB0[t0 & 3] = fast_exp2(emB[t0 * CD + j0] * LOG2E);
        WrB1[t0 & 3] = fast_exp2(emB[t0 * CD + j1] * LOG2E);
        mrB[t0 & 3]  = mkB[t0];
    }
    __syncwarp();

    // ---- recursion: t = 1..1020 in chunks of 4 (compile-time slots),
    //      then 1021..1023 peeled. ----
    float logAccA = 0.f, logAccB = 0.f;
    int   cur = 0;

    for (int tb = 1; tb + 3 < TD; tb += 4) {   // tb = 1, 5, ..., 1017
        STEP2(tb + 0, 1) STEP2(tb + 1, 2) STEP2(tb + 2, 3) STEP2(tb + 3, 0)
    }
    STEP2(1021, 1) STEP2(1022, 2) STEP2(1023, 3)

    // ---- final logsumexp per chain ----
    const float e0 = fast_exp2(end_t[j0] * LOG2E);
    const float e1 = fast_exp2(end_t[j1] * LOG2E);
    float vA = mypA0 * e0 + mypA1 * e1;
    float vB = mypB0 * e0 + mypB1 * e1;
    #pragma unroll
    for (int off = 16; off; off >>= 1) {
        vA += __shfl_xor_sync(0xffffffffu, vA, off);
        vB += __shfl_xor_sync(0xffffffffu, vB, off);
    }
    if (lane == 0) {
        g_partial[bA] = (logAccA + fast_log2(vA)) * LN2 - goldA;
        g_partial[bB] = (logAccB + fast_log2(vB)) * LN2 - goldB;
    }

    // ---- fused deterministic mean reduction (last block) ----
    __syncthreads();
    if (threadIdx.x == 0) {
        __threadfence();
        unsigned int tk = atomicAdd(&g_done, 1u);
        last_flag = (tk == gridDim.x - 1) ? 1u : 0u;
    }
    __syncthreads();

    if (last_flag) {
        __threadfence();
        float s = g_partial[threadIdx.x] + g_partial[threadIdx.x + 128];
        #pragma unroll
        for (int off = 16; off; off >>= 1)
            s += __shfl_xor_sync(0xffffffffu, s, off);
        if (lane == 0) rsm[w] = s;
        __syncthreads();
        if (threadIdx.x == 0) {
            out[0] = (rsm[0] + rsm[1] + rsm[2] + rsm[3]) * (1.0f / BD);
            g_done = 0;                    // reset for next graph replay
        }
    }
}

extern "C" void kernel_launch(void* const* d_in, const int* in_sizes, int n_in,
                              void* d_out, int out_size)
{
    const float* emissions   = (const float*)d_in[0];
    const float* transitions = (const float*)d_in[1];
    const float* start_t     = (const float*)d_in[2];
    const float* end_t       = (const float*)d_in[3];
    const int*   tags        = (const int*)  d_in[4];
    const float* mask        = (const float*)d_in[5];
    float* out = (float*)d_out;

    crf_fused_kernel<<<BD / 8, 128>>>(emissions, transitions, start_t, end_t,
                                      tags, mask, out);
}

// round 12
// speedup vs baseline: 1.7125x; 1.7125x over previous
#include <cuda_runtime.h>
#include <cstdint>

// CRF loss: mean_b( logZ_b - gold_b );  B=256, T=1024, C=64
// Scaled-domain forward: p_{t+1} = (E^T p_t) ∘ W_t / c_t,  logZ += log2 c_t.
// One warp per chain (2 tags/thread). Critical-path diet:
//  - normalizer (c, r=rcp, log2 c, W*r, mask) staged ONE STEP AHEAD via shfl,
//    so the in-step chain is sync -> LDS -> FFMA2 tree -> packed-sum -> mul/sel -> STS
//  - prefetch guard branch removed (main loop unconditional, tail fully peeled)
//  - packed f32x2 adds for the sum tree
// Grid 64 x 128thr: 4 chains/block, 1 warp/SMSP. Reduction fused.

#define BD 256
#define TD 1024
#define CD 64
#define LOG2E 1.4426950408889634f
#define LN2   0.6931471805599453f

typedef unsigned long long ull;

__device__ float        g_partial[BD];
__device__ unsigned int g_done = 0;

__device__ __forceinline__ float fast_exp2(float x) {
    float y; asm("ex2.approx.ftz.f32 %0, %1;" : "=f"(y) : "f"(x)); return y;
}
__device__ __forceinline__ float fast_log2(float x) {
    float y; asm("lg2.approx.ftz.f32 %0, %1;" : "=f"(y) : "f"(x)); return y;
}
__device__ __forceinline__ float fast_rcp(float x) {
    float y; asm("rcp.approx.ftz.f32 %0, %1;" : "=f"(y) : "f"(x)); return y;
}
__device__ __forceinline__ ull pack2(float lo, float hi) {
    ull r; asm("mov.b64 %0, {%1, %2};" : "=l"(r) : "f"(lo), "f"(hi)); return r;
}
__device__ __forceinline__ ull ffma2(ull a, ull b, ull c) {
    ull d; asm("fma.rn.f32x2 %0, %1, %2, %3;" : "=l"(d) : "l"(a), "l"(b), "l"(c));
    return d;
}
__device__ __forceinline__ ull fadd2(ull a, ull b) {
    ull d; asm("add.rn.f32x2 %0, %1, %2;" : "=l"(d) : "l"(a), "l"(b));
    return d;
}
__device__ __forceinline__ float2 unpack2(ull v) {
    float2 f; asm("mov.b64 {%0, %1}, %2;" : "=f"(f.x), "=f"(f.y) : "l"(v));
    return f;
}

// One forward step. T_/SLOT_/NSLOT_ compile-time. PF_: do ring refill.
// Consumes staged {rS, lgcS, mtS, Wr0S, Wr1S}; stages the next step's set.
#define STEP_BODY(PF_, T_, SLOT_, NSLOT_)                                      \
    {                                                                          \
        logAcc += lgcS;                                                        \
        if (PF_) {                                                             \
            const int tpf = (T_) + 8;                                          \
            Wring0[(SLOT_)] = fast_exp2(em[tpf * CD + j0] * LOG2E);            \
            Wring1[(SLOT_)] = fast_exp2(em[tpf * CD + j1] * LOG2E);            \
            mr[(SLOT_)]     = mk[tpf];                                         \
        }                                                                      \
        const float* pc = psh[w][cur];                                         \
        ull a0 = 0ull, a1 = 0ull, a2 = 0ull, a3 = 0ull;                        \
        ull b0 = 0ull, b1 = 0ull, b2 = 0ull, b3 = 0ull;                        \
        _Pragma("unroll")                                                      \
        for (int i = 0; i < CD; i += 8) {                                      \
            ulonglong2 qa = *(const ulonglong2*)&pc[i];                        \
            ulonglong2 qb = *(const ulonglong2*)&pc[i + 4];                    \
            a0 = ffma2(qa.x, E0p[i / 2 + 0], a0);                              \
            b0 = ffma2(qa.x, E1p[i / 2 + 0], b0);                              \
            a1 = ffma2(qa.y, E0p[i / 2 + 1], a1);                              \
            b1 = ffma2(qa.y, E1p[i / 2 + 1], b1);                              \
            a2 = ffma2(qb.x, E0p[i / 2 + 2], a2);                              \
            b2 = ffma2(qb.x, E1p[i / 2 + 2], b2);                              \
            a3 = ffma2(qb.y, E0p[i / 2 + 3], a3);                              \
            b3 = ffma2(qb.y, E1p[i / 2 + 3], b3);                              \
        }                                                                      \
        const ull ta = fadd2(fadd2(a0, a1), fadd2(a2, a3));                    \
        const ull tb = fadd2(fadd2(b0, b1), fadd2(b2, b3));                    \
        const float2 ua = unpack2(ta);                                         \
        const float2 ub = unpack2(tb);                                         \
        const float s0 = ua.x + ua.y;                                          \
        const float s1 = ub.x + ub.y;                                          \
        myp0 = (mtS > 0.f) ? s0 * Wr0S : myp0 * rS;                            \
        myp1 = (mtS > 0.f) ? s1 * Wr1S : myp1 * rS;                            \
        float* pn = psh[w][cur ^ 1];                                           \
        pn[j0] = myp0;                                                         \
        pn[j1] = myp1;                                                         \
        const float cN = __shfl_sync(0xffffffffu, myp0, 0);                    \
        rS   = fast_rcp(cN);                                                   \
        lgcS = fast_log2(cN);                                                  \
        mtS  = mr[(NSLOT_)];                                                   \
        Wr0S = Wring0[(NSLOT_)] * rS;                                          \
        Wr1S = Wring1[(NSLOT_)] * rS;                                          \
        __syncwarp();                                                          \
        cur ^= 1;                                                              \
    }

__global__ __launch_bounds__(128)
void crf_fused_kernel(const float* __restrict__ emissions,
                      const float* __restrict__ transitions,
                      const float* __restrict__ start_t,
                      const float* __restrict__ end_t,
                      const int*   __restrict__ tags,
                      const float* __restrict__ mask,
                      float*       __restrict__ out)
{
    __shared__ __align__(16) float psh[4][2][CD];  // [chain][buf][tag]
    __shared__ float        rsm[4];
    __shared__ unsigned int last_flag;

    const int w    = threadIdx.x >> 5;    // chain within block (0..3)
    const int lane = threadIdx.x & 31;
    const int b    = blockIdx.x * 4 + w;  // batch index
    const int j0   = lane;
    const int j1   = lane + 32;

    const float* em = emissions + (size_t)b * TD * CD;
    const int*   tg = tags      + (size_t)b * TD;
    const float* mk = mask      + (size_t)b * TD;

    // ---- packed E columns: E?p[k] = {exp(T[2k][j?]), exp(T[2k+1][j?])} ----
    ull E0p[CD / 2], E1p[CD / 2];
    #pragma unroll
    for (int k = 0; k < CD / 2; k++) {
        const float* r0 = transitions + (2 * k)     * CD;
        const float* r1 = transitions + (2 * k + 1) * CD;
        E0p[k] = pack2(fast_exp2(r0[j0] * LOG2E), fast_exp2(r1[j0] * LOG2E));
        E1p[k] = pack2(fast_exp2(r0[j1] * LOG2E), fast_exp2(r1[j1] * LOG2E));
    }

    // ---- gold score (32 threads stride T) ----
    float gp  = 0.f;
    int   cnt = 0;
    for (int t = lane; t < TD; t += 32) {
        float m = mk[t];
        cnt += (int)m;
        if (t >= 1) {
            int tc = tg[t], tp = tg[t - 1];
            gp += m * (em[t * CD + tc] + transitions[tp * CD + tc]);
        }
    }
    #pragma unroll
    for (int off = 16; off; off >>= 1) {
        gp  += __shfl_xor_sync(0xffffffffu, gp,  off);
        cnt += __shfl_xor_sync(0xffffffffu, cnt, off);
    }
    int lastidx = cnt - 1; if (lastidx < 0) lastidx = 0;
    const int tfirst = tg[0], tlast = tg[lastidx];              // broadcast LDG
    const float gold = gp + start_t[tfirst] + em[tfirst] + end_t[tlast];

    // ---- init (t = 0), linear domain ----
    float myp0 = fast_exp2((start_t[j0] + em[j0]) * LOG2E);
    float myp1 = fast_exp2((start_t[j1] + em[j1]) * LOG2E);
    psh[w][0][j0] = myp0;
    psh[w][0][j1] = myp1;

    // ---- prefetch ring (8 deep): raw W = exp(emit), mask ----
    float Wring0[8], Wring1[8], mr[8];
    #pragma unroll
    for (int t0 = 1; t0 <= 8; t0++) {
        Wring0[t0 & 7] = fast_exp2(em[t0 * CD + j0] * LOG2E);
        Wring1[t0 & 7] = fast_exp2(em[t0 * CD + j1] * LOG2E);
        mr[t0 & 7]     = mk[t0];
    }

    // ---- stage for step t=1 ----
    float cN   = __shfl_sync(0xffffffffu, myp0, 0);   // c_0 = p_0[0]
    float rS   = fast_rcp(cN);
    float lgcS = fast_log2(cN);
    float mtS  = mr[1];
    float Wr0S = Wring0[1] * rS;
    float Wr1S = Wring1[1] * rS;

    __syncwarp();   // psh[w][0] visible

    // ---- recursion ----
    float logAcc = 0.f;
    int   cur    = 0;

    // main loop: t = 1..1008 (126 chunks of 8), unconditional prefetch
    for (int tb = 1; tb <= 1001; tb += 8) {
        STEP_BODY(1, tb + 0, 1, 2) STEP_BODY(1, tb + 1, 2, 3)
        STEP_BODY(1, tb + 2, 3, 4) STEP_BODY(1, tb + 3, 4, 5)
        STEP_BODY(1, tb + 4, 5, 6) STEP_BODY(1, tb + 5, 6, 7)
        STEP_BODY(1, tb + 6, 7, 0) STEP_BODY(1, tb + 7, 0, 1)
    }
    // t = 1009..1015: prefetch t+8 = 1017..1023 (still in range)
    STEP_BODY(1, 1009, 1, 2) STEP_BODY(1, 1010, 2, 3) STEP_BODY(1, 1011, 3, 4)
    STEP_BODY(1, 1012, 4, 5) STEP_BODY(1, 1013, 5, 6) STEP_BODY(1, 1014, 6, 7)
    STEP_BODY(1, 1015, 7, 0)
    // t = 1016..1023: no prefetch
    STEP_BODY(0, 1016, 0, 1) STEP_BODY(0, 1017, 1, 2) STEP_BODY(0, 1018, 2, 3)
    STEP_BODY(0, 1019, 3, 4) STEP_BODY(0, 1020, 4, 5) STEP_BODY(0, 1021, 5, 6)
    STEP_BODY(0, 1022, 6, 7) STEP_BODY(0, 1023, 7, 0)

    // ---- final: logZ = LN2 * (logAcc + log2(sum_j p_j * exp(end_j))) ----
    float v = myp0 * fast_exp2(end_t[j0] * LOG2E)
            + myp1 * fast_exp2(end_t[j1] * LOG2E);
    #pragma unroll
    for (int off = 16; off; off >>= 1)
        v += __shfl_xor_sync(0xffffffffu, v, off);

    if (lane == 0)
        g_partial[b] = (logAcc + fast_log2(v)) * LN2 - gold;

    // ---- fused deterministic mean reduction (last block) ----
    __syncthreads();                       // all 4 chains' g_partial writes done
    if (threadIdx.x == 0) {
        __threadfence();                   // publish this block's writes
        unsigned int tk = atomicAdd(&g_done, 1u);
        last_flag = (tk == gridDim.x - 1) ? 1u : 0u;
    }
    __syncthreads();

    if (last_flag) {
        __threadfence();                   // acquire all blocks' writes
        float s = g_partial[threadIdx.x] + g_partial[threadIdx.x + 128];
        #pragma unroll
        for (int off = 16; off; off >>= 1)
            s += __shfl_xor_sync(0xffffffffu, s, off);
        if (lane == 0) rsm[w] = s;
        __syncthreads();
        if (threadIdx.x == 0) {
            out[0] = (rsm[0] + rsm[1] + rsm[2] + rsm[3]) * (1.0f / BD);
            g_done = 0;                    // reset for next graph replay
        }
    }
}

extern "C" void kernel_launch(void* const* d_in, const int* in_sizes, int n_in,
                              void* d_out, int out_size)
{
    const float* emissions   = (const float*)d_in[0];
    const float* transitions = (const float*)d_in[1];
    const float* start_t     = (const float*)d_in[2];
    const float* end_t       = (const float*)d_in[3];
    const int*   tags        = (const int*)  d_in[4];
    const float* mask        = (const float*)d_in[5];
    float* out = (float*)d_out;

    crf_fused_kernel<<<BD / 4, 128>>>(emissions, transitions, start_t, end_t,
                                      tags, mask, out);
}